// round 1
// baseline (speedup 1.0000x reference)
#include <cuda_runtime.h>
#include <cuda_bf16.h>

// ---------------------------------------------------------------------------
// BiaffineSpan: out[b,i,j,c] =
//   sum_{d,e} Hs[b,i,d] * W1[c,d,e] * He[b,j,e]       (bilinear)
//   + Ls[b,i,c] + Le[b,j,c] + W2_b[c] + bias[c]       (linear)
// where Hs = MLP(x; sw1,sb1,sw2,sb2), He = MLP(x; ew*,eb*),
//       Ls = Hs @ W2_w[:, :D].T, Le = He @ W2_w[:, D:].T
//
// B=2, L=512, D=768, C=256.  All GEMM dims divide 128/8 exactly.
// ---------------------------------------------------------------------------

#define Dd 768
#define Cc 256
#define BL 1024            // B*L
#define Lq 512

// Scratch (device globals: allocation-free rule)
__device__ float g_Htmp[BL * Dd];
__device__ float g_Hs[BL * Dd];
__device__ float g_He[BL * Dd];
__device__ float g_Ls[BL * Cc];
__device__ float g_Le[BL * Cc];
__device__ float g_T[(long)BL * Cc * Dd];   // 805 MB: T[bi][c][e]

#define BM 128
#define BN 128
#define BK 8
#define TM 8
#define TN 8

// Generic 128x128x8 SGEMM.
// NT==1: C[m,n] = sum_k A[m,k] * B[n,k]   (B row-major [N,K])
// NT==0: C[m,n] = sum_k A[m,k] * B[k,n]   (B row-major [K,N])
// Per-z strides for batched use. Optional per-column bias and relu.
template <int NT>
__global__ void __launch_bounds__(256)
sgemm_k(const float* __restrict__ A, long saz, int lda,
        const float* __restrict__ B, long sbz, int ldb,
        float* __restrict__ C, long scz, int ldc,
        int K, const float* __restrict__ bias, int relu)
{
    __shared__ float As[BK][BM];
    __shared__ float Bs[BK][BN];

    const int z = blockIdx.z;
    A += (long)z * saz;
    B += (long)z * sbz;
    C += (long)z * scz;

    const int m0 = blockIdx.y * BM;
    const int n0 = blockIdx.x * BN;
    const int tid = threadIdx.x;
    const int tx = tid & 15;
    const int ty = tid >> 4;

    const int aRow = tid >> 1;         // 0..127
    const int aCol = (tid & 1) * 4;    // 0 or 4
    const int bRow = tid >> 5;         // 0..7   (NN)
    const int bCol = (tid & 31) * 4;   // 0..124 (NN)

    float acc[TM][TN];
#pragma unroll
    for (int i = 0; i < TM; i++)
#pragma unroll
        for (int j = 0; j < TN; j++) acc[i][j] = 0.f;

    for (int k0 = 0; k0 < K; k0 += BK) {
        float4 av = *(const float4*)(A + (long)(m0 + aRow) * lda + k0 + aCol);
        As[aCol + 0][aRow] = av.x;
        As[aCol + 1][aRow] = av.y;
        As[aCol + 2][aRow] = av.z;
        As[aCol + 3][aRow] = av.w;
        if (NT) {
            float4 bv = *(const float4*)(B + (long)(n0 + aRow) * ldb + k0 + aCol);
            Bs[aCol + 0][aRow] = bv.x;
            Bs[aCol + 1][aRow] = bv.y;
            Bs[aCol + 2][aRow] = bv.z;
            Bs[aCol + 3][aRow] = bv.w;
        } else {
            float4 bv = *(const float4*)(B + (long)(k0 + bRow) * ldb + n0 + bCol);
            *(float4*)&Bs[bRow][bCol] = bv;
        }
        __syncthreads();

#pragma unroll
        for (int kk = 0; kk < BK; kk++) {
            float4 a0 = *(const float4*)&As[kk][ty * TM];
            float4 a1 = *(const float4*)&As[kk][ty * TM + 4];
            float4 b0 = *(const float4*)&Bs[kk][tx * TN];
            float4 b1 = *(const float4*)&Bs[kk][tx * TN + 4];
            float ra[TM] = {a0.x, a0.y, a0.z, a0.w, a1.x, a1.y, a1.z, a1.w};
            float rb[TN] = {b0.x, b0.y, b0.z, b0.w, b1.x, b1.y, b1.z, b1.w};
#pragma unroll
            for (int i = 0; i < TM; i++)
#pragma unroll
                for (int j = 0; j < TN; j++)
                    acc[i][j] = fmaf(ra[i], rb[j], acc[i][j]);
        }
        __syncthreads();
    }

#pragma unroll
    for (int i = 0; i < TM; i++) {
        const long row = m0 + ty * TM + i;
#pragma unroll
        for (int j = 0; j < TN; j++) {
            const int col = n0 + tx * TN + j;
            float v = acc[i][j];
            if (bias) v += bias[col];
            if (relu) v = fmaxf(v, 0.f);
            C[row * (long)ldc + col] = v;
        }
    }
}

// Phase B: for z = b*512+i:
//   out[z, j, c] = sum_e He[b,j,e] * T[z,c,e]
//                  + Ls[z,c] + Le[b*512+j, c] + W2_b[c] + bias[c]
// M=512 (j), N=256 (c), K=768 (e). NT layout for both operands.
__global__ void __launch_bounds__(256)
phaseB_k(const float* __restrict__ He, const float* __restrict__ T,
         const float* __restrict__ Ls, const float* __restrict__ Le,
         const float* __restrict__ W2b, const float* __restrict__ bias,
         float* __restrict__ out)
{
    __shared__ float As[BK][BM];
    __shared__ float Bs[BK][BN];

    const int z = blockIdx.z;          // 0..1023
    const int b = z >> 9;
    const float* A = He + (long)b * Lq * Dd;      // [512, 768] rows j
    const float* Bm = T + (long)z * Cc * Dd;      // [256, 768] rows c
    float* C = out + (long)z * Lq * Cc;
    const float* lsr = Ls + (long)z * Cc;
    const float* leb = Le + (long)b * Lq * Cc;

    const int m0 = blockIdx.y * BM;    // j tile
    const int n0 = blockIdx.x * BN;    // c tile
    const int tid = threadIdx.x;
    const int tx = tid & 15;
    const int ty = tid >> 4;

    const int aRow = tid >> 1;
    const int aCol = (tid & 1) * 4;

    float acc[TM][TN];
#pragma unroll
    for (int i = 0; i < TM; i++)
#pragma unroll
        for (int j = 0; j < TN; j++) acc[i][j] = 0.f;

    for (int k0 = 0; k0 < Dd; k0 += BK) {
        float4 av = *(const float4*)(A + (long)(m0 + aRow) * Dd + k0 + aCol);
        As[aCol + 0][aRow] = av.x;
        As[aCol + 1][aRow] = av.y;
        As[aCol + 2][aRow] = av.z;
        As[aCol + 3][aRow] = av.w;
        float4 bv = *(const float4*)(Bm + (long)(n0 + aRow) * Dd + k0 + aCol);
        Bs[aCol + 0][aRow] = bv.x;
        Bs[aCol + 1][aRow] = bv.y;
        Bs[aCol + 2][aRow] = bv.z;
        Bs[aCol + 3][aRow] = bv.w;
        __syncthreads();

#pragma unroll
        for (int kk = 0; kk < BK; kk++) {
            float4 a0 = *(const float4*)&As[kk][ty * TM];
            float4 a1 = *(const float4*)&As[kk][ty * TM + 4];
            float4 b0 = *(const float4*)&Bs[kk][tx * TN];
            float4 b1 = *(const float4*)&Bs[kk][tx * TN + 4];
            float ra[TM] = {a0.x, a0.y, a0.z, a0.w, a1.x, a1.y, a1.z, a1.w};
            float rb[TN] = {b0.x, b0.y, b0.z, b0.w, b1.x, b1.y, b1.z, b1.w};
#pragma unroll
            for (int i = 0; i < TM; i++)
#pragma unroll
                for (int j = 0; j < TN; j++)
                    acc[i][j] = fmaf(ra[i], rb[j], acc[i][j]);
        }
        __syncthreads();
    }

    // per-column (c) additive term, shared across rows
    float coladd[TN];
#pragma unroll
    for (int j = 0; j < TN; j++) {
        const int c = n0 + tx * TN + j;
        coladd[j] = lsr[c] + W2b[c] + bias[c];
    }

#pragma unroll
    for (int i = 0; i < TM; i++) {
        const int jrow = m0 + ty * TM + i;
        const float* lerow = leb + (long)jrow * Cc;
        float* crow = C + (long)jrow * Cc;
#pragma unroll
        for (int j = 0; j < TN; j++) {
            const int c = n0 + tx * TN + j;
            crow[c] = acc[i][j] + coladd[j] + lerow[c];
        }
    }
}

extern "C" void kernel_launch(void* const* d_in, const int* in_sizes, int n_in,
                              void* d_out, int out_size)
{
    const float* hidden = (const float*)d_in[0];   // [2,512,768]
    const float* sw1 = (const float*)d_in[1];
    const float* sb1 = (const float*)d_in[2];
    const float* sw2 = (const float*)d_in[3];
    const float* sb2 = (const float*)d_in[4];
    const float* ew1 = (const float*)d_in[5];
    const float* eb1 = (const float*)d_in[6];
    const float* ew2 = (const float*)d_in[7];
    const float* eb2 = (const float*)d_in[8];
    const float* W1  = (const float*)d_in[9];      // [256,768,768]
    const float* W2w = (const float*)d_in[10];     // [256,1536]
    const float* W2b = (const float*)d_in[11];     // [256]
    const float* bs  = (const float*)d_in[12];     // [256]
    float* out = (float*)d_out;

    float *Htmp, *Hs, *He, *Ls, *Le, *T;
    cudaGetSymbolAddress((void**)&Htmp, g_Htmp);
    cudaGetSymbolAddress((void**)&Hs, g_Hs);
    cudaGetSymbolAddress((void**)&He, g_He);
    cudaGetSymbolAddress((void**)&Ls, g_Ls);
    cudaGetSymbolAddress((void**)&Le, g_Le);
    cudaGetSymbolAddress((void**)&T, g_T);

    dim3 blk(256);

    // MLPs:  h = relu(x@w1.T + b1); H = h@w2.T + b2     M=1024, N=768, K=768
    sgemm_k<1><<<dim3(6, 8, 1), blk>>>(hidden, 0, Dd, sw1, 0, Dd, Htmp, 0, Dd, Dd, sb1, 1);
    sgemm_k<1><<<dim3(6, 8, 1), blk>>>(Htmp,   0, Dd, sw2, 0, Dd, Hs,   0, Dd, Dd, sb2, 0);
    sgemm_k<1><<<dim3(6, 8, 1), blk>>>(hidden, 0, Dd, ew1, 0, Dd, Htmp, 0, Dd, Dd, eb1, 1);
    sgemm_k<1><<<dim3(6, 8, 1), blk>>>(Htmp,   0, Dd, ew2, 0, Dd, He,   0, Dd, Dd, eb2, 0);

    // Ls = Hs @ W2_w[:, :D].T ; Le = He @ W2_w[:, D:].T   M=1024, N=256, K=768
    sgemm_k<1><<<dim3(2, 8, 1), blk>>>(Hs, 0, Dd, W2w,      0, 2 * Dd, Ls, 0, Cc, Dd, nullptr, 0);
    sgemm_k<1><<<dim3(2, 8, 1), blk>>>(He, 0, Dd, W2w + Dd, 0, 2 * Dd, Le, 0, Cc, Dd, nullptr, 0);

    // Phase A: T[bi, c, e] = sum_d Hs[bi, d] * W1[c, d, e]
    // z = c: A = Hs [1024,768], B = W1[c] [768,768] (NN), C row-stride = C*D
    sgemm_k<0><<<dim3(6, 8, Cc), blk>>>(Hs, 0, Dd,
                                        W1, (long)Dd * Dd, Dd,
                                        T, (long)Dd, Cc * Dd,
                                        Dd, nullptr, 0);

    // Phase B: out[z, j, c] = He_b[j,:] . T[z,c,:] + linear terms
    phaseB_k<<<dim3(2, 4, BL), blk>>>(He, T, Ls, Le, W2b, bs, out);
}

// round 2
// speedup vs baseline: 1.0010x; 1.0010x over previous
#include <cuda_runtime.h>
#include <cuda_bf16.h>

// ---------------------------------------------------------------------------
// BiaffineSpan: out[b,i,j,c] =
//   sum_{d,e} Hs[b,i,d] * W1[c,d,e] * He[b,j,e]       (bilinear)
//   + Ls[b,i,c] + Le[b,j,c] + W2_b[c] + bias[c]       (linear)
// where Hs = MLP(x; sw1,sb1,sw2,sb2), He = MLP(x; ew*,eb*),
//       Ls = Hs @ W2_w[:, :D].T, Le = He @ W2_w[:, D:].T
//
// B=2, L=512, D=768, C=256.  All GEMM dims divide 128/8 exactly.
// ---------------------------------------------------------------------------

#define Dd 768
#define Cc 256
#define BL 1024            // B*L
#define Lq 512

// Scratch (device globals: allocation-free rule)
__device__ float g_Htmp[BL * Dd];
__device__ float g_Hs[BL * Dd];
__device__ float g_He[BL * Dd];
__device__ float g_Ls[BL * Cc];
__device__ float g_Le[BL * Cc];
__device__ float g_T[(long)BL * Cc * Dd];   // 805 MB: T[bi][c][e]

#define BM 128
#define BN 128
#define BK 8
#define TM 8
#define TN 8

// Generic 128x128x8 SGEMM.
// NT==1: C[m,n] = sum_k A[m,k] * B[n,k]   (B row-major [N,K])
// NT==0: C[m,n] = sum_k A[m,k] * B[k,n]   (B row-major [K,N])
// Per-z strides for batched use. Optional per-column bias and relu.
template <int NT>
__global__ void __launch_bounds__(256)
sgemm_k(const float* __restrict__ A, long saz, int lda,
        const float* __restrict__ B, long sbz, int ldb,
        float* __restrict__ C, long scz, int ldc,
        int K, const float* __restrict__ bias, int relu)
{
    __shared__ float As[BK][BM];
    __shared__ float Bs[BK][BN];

    const int z = blockIdx.z;
    A += (long)z * saz;
    B += (long)z * sbz;
    C += (long)z * scz;

    const int m0 = blockIdx.y * BM;
    const int n0 = blockIdx.x * BN;
    const int tid = threadIdx.x;
    const int tx = tid & 15;
    const int ty = tid >> 4;

    const int aRow = tid >> 1;         // 0..127
    const int aCol = (tid & 1) * 4;    // 0 or 4
    const int bRow = tid >> 5;         // 0..7   (NN)
    const int bCol = (tid & 31) * 4;   // 0..124 (NN)

    float acc[TM][TN];
#pragma unroll
    for (int i = 0; i < TM; i++)
#pragma unroll
        for (int j = 0; j < TN; j++) acc[i][j] = 0.f;

    for (int k0 = 0; k0 < K; k0 += BK) {
        float4 av = *(const float4*)(A + (long)(m0 + aRow) * lda + k0 + aCol);
        As[aCol + 0][aRow] = av.x;
        As[aCol + 1][aRow] = av.y;
        As[aCol + 2][aRow] = av.z;
        As[aCol + 3][aRow] = av.w;
        if (NT) {
            float4 bv = *(const float4*)(B + (long)(n0 + aRow) * ldb + k0 + aCol);
            Bs[aCol + 0][aRow] = bv.x;
            Bs[aCol + 1][aRow] = bv.y;
            Bs[aCol + 2][aRow] = bv.z;
            Bs[aCol + 3][aRow] = bv.w;
        } else {
            float4 bv = *(const float4*)(B + (long)(k0 + bRow) * ldb + n0 + bCol);
            *(float4*)&Bs[bRow][bCol] = bv;
        }
        __syncthreads();

#pragma unroll
        for (int kk = 0; kk < BK; kk++) {
            float4 a0 = *(const float4*)&As[kk][ty * TM];
            float4 a1 = *(const float4*)&As[kk][ty * TM + 4];
            float4 b0 = *(const float4*)&Bs[kk][tx * TN];
            float4 b1 = *(const float4*)&Bs[kk][tx * TN + 4];
            float ra[TM] = {a0.x, a0.y, a0.z, a0.w, a1.x, a1.y, a1.z, a1.w};
            float rb[TN] = {b0.x, b0.y, b0.z, b0.w, b1.x, b1.y, b1.z, b1.w};
#pragma unroll
            for (int i = 0; i < TM; i++)
#pragma unroll
                for (int j = 0; j < TN; j++)
                    acc[i][j] = fmaf(ra[i], rb[j], acc[i][j]);
        }
        __syncthreads();
    }

#pragma unroll
    for (int i = 0; i < TM; i++) {
        const long row = m0 + ty * TM + i;
#pragma unroll
        for (int j = 0; j < TN; j++) {
            const int col = n0 + tx * TN + j;
            float v = acc[i][j];
            if (bias) v += bias[col];
            if (relu) v = fmaxf(v, 0.f);
            C[row * (long)ldc + col] = v;
        }
    }
}

// Phase B: for z = b*512+i:
//   out[z, j, c] = sum_e He[b,j,e] * T[z,c,e]
//                  + Ls[z,c] + Le[b*512+j, c] + W2_b[c] + bias[c]
// M=512 (j), N=256 (c), K=768 (e). NT layout for both operands.
__global__ void __launch_bounds__(256)
phaseB_k(const float* __restrict__ He, const float* __restrict__ T,
         const float* __restrict__ Ls, const float* __restrict__ Le,
         const float* __restrict__ W2b, const float* __restrict__ bias,
         float* __restrict__ out)
{
    __shared__ float As[BK][BM];
    __shared__ float Bs[BK][BN];

    const int z = blockIdx.z;          // 0..1023
    const int b = z >> 9;
    const float* A = He + (long)b * Lq * Dd;      // [512, 768] rows j
    const float* Bm = T + (long)z * Cc * Dd;      // [256, 768] rows c
    float* C = out + (long)z * Lq * Cc;
    const float* lsr = Ls + (long)z * Cc;
    const float* leb = Le + (long)b * Lq * Cc;

    const int m0 = blockIdx.y * BM;    // j tile
    const int n0 = blockIdx.x * BN;    // c tile
    const int tid = threadIdx.x;
    const int tx = tid & 15;
    const int ty = tid >> 4;

    const int aRow = tid >> 1;
    const int aCol = (tid & 1) * 4;

    float acc[TM][TN];
#pragma unroll
    for (int i = 0; i < TM; i++)
#pragma unroll
        for (int j = 0; j < TN; j++) acc[i][j] = 0.f;

    for (int k0 = 0; k0 < Dd; k0 += BK) {
        float4 av = *(const float4*)(A + (long)(m0 + aRow) * Dd + k0 + aCol);
        As[aCol + 0][aRow] = av.x;
        As[aCol + 1][aRow] = av.y;
        As[aCol + 2][aRow] = av.z;
        As[aCol + 3][aRow] = av.w;
        float4 bv = *(const float4*)(Bm + (long)(n0 + aRow) * Dd + k0 + aCol);
        Bs[aCol + 0][aRow] = bv.x;
        Bs[aCol + 1][aRow] = bv.y;
        Bs[aCol + 2][aRow] = bv.z;
        Bs[aCol + 3][aRow] = bv.w;
        __syncthreads();

#pragma unroll
        for (int kk = 0; kk < BK; kk++) {
            float4 a0 = *(const float4*)&As[kk][ty * TM];
            float4 a1 = *(const float4*)&As[kk][ty * TM + 4];
            float4 b0 = *(const float4*)&Bs[kk][tx * TN];
            float4 b1 = *(const float4*)&Bs[kk][tx * TN + 4];
            float ra[TM] = {a0.x, a0.y, a0.z, a0.w, a1.x, a1.y, a1.z, a1.w};
            float rb[TN] = {b0.x, b0.y, b0.z, b0.w, b1.x, b1.y, b1.z, b1.w};
#pragma unroll
            for (int i = 0; i < TM; i++)
#pragma unroll
                for (int j = 0; j < TN; j++)
                    acc[i][j] = fmaf(ra[i], rb[j], acc[i][j]);
        }
        __syncthreads();
    }

    // per-column (c) additive term, shared across rows
    float coladd[TN];
#pragma unroll
    for (int j = 0; j < TN; j++) {
        const int c = n0 + tx * TN + j;
        coladd[j] = lsr[c] + W2b[c] + bias[c];
    }

#pragma unroll
    for (int i = 0; i < TM; i++) {
        const int jrow = m0 + ty * TM + i;
        const float* lerow = leb + (long)jrow * Cc;
        float* crow = C + (long)jrow * Cc;
#pragma unroll
        for (int j = 0; j < TN; j++) {
            const int c = n0 + tx * TN + j;
            crow[c] = acc[i][j] + coladd[j] + lerow[c];
        }
    }
}

extern "C" void kernel_launch(void* const* d_in, const int* in_sizes, int n_in,
                              void* d_out, int out_size)
{
    const float* hidden = (const float*)d_in[0];   // [2,512,768]
    const float* sw1 = (const float*)d_in[1];
    const float* sb1 = (const float*)d_in[2];
    const float* sw2 = (const float*)d_in[3];
    const float* sb2 = (const float*)d_in[4];
    const float* ew1 = (const float*)d_in[5];
    const float* eb1 = (const float*)d_in[6];
    const float* ew2 = (const float*)d_in[7];
    const float* eb2 = (const float*)d_in[8];
    const float* W1  = (const float*)d_in[9];      // [256,768,768]
    const float* W2w = (const float*)d_in[10];     // [256,1536]
    const float* W2b = (const float*)d_in[11];     // [256]
    const float* bs  = (const float*)d_in[12];     // [256]
    float* out = (float*)d_out;

    float *Htmp, *Hs, *He, *Ls, *Le, *T;
    cudaGetSymbolAddress((void**)&Htmp, g_Htmp);
    cudaGetSymbolAddress((void**)&Hs, g_Hs);
    cudaGetSymbolAddress((void**)&He, g_He);
    cudaGetSymbolAddress((void**)&Ls, g_Ls);
    cudaGetSymbolAddress((void**)&Le, g_Le);
    cudaGetSymbolAddress((void**)&T, g_T);

    dim3 blk(256);

    // MLPs:  h = relu(x@w1.T + b1); H = h@w2.T + b2     M=1024, N=768, K=768
    sgemm_k<1><<<dim3(6, 8, 1), blk>>>(hidden, 0, Dd, sw1, 0, Dd, Htmp, 0, Dd, Dd, sb1, 1);
    sgemm_k<1><<<dim3(6, 8, 1), blk>>>(Htmp,   0, Dd, sw2, 0, Dd, Hs,   0, Dd, Dd, sb2, 0);
    sgemm_k<1><<<dim3(6, 8, 1), blk>>>(hidden, 0, Dd, ew1, 0, Dd, Htmp, 0, Dd, Dd, eb1, 1);
    sgemm_k<1><<<dim3(6, 8, 1), blk>>>(Htmp,   0, Dd, ew2, 0, Dd, He,   0, Dd, Dd, eb2, 0);

    // Ls = Hs @ W2_w[:, :D].T ; Le = He @ W2_w[:, D:].T   M=1024, N=256, K=768
    sgemm_k<1><<<dim3(2, 8, 1), blk>>>(Hs, 0, Dd, W2w,      0, 2 * Dd, Ls, 0, Cc, Dd, nullptr, 0);
    sgemm_k<1><<<dim3(2, 8, 1), blk>>>(He, 0, Dd, W2w + Dd, 0, 2 * Dd, Le, 0, Cc, Dd, nullptr, 0);

    // Phase A: T[bi, c, e] = sum_d Hs[bi, d] * W1[c, d, e]
    // z = c: A = Hs [1024,768], B = W1[c] [768,768] (NN), C row-stride = C*D
    sgemm_k<0><<<dim3(6, 8, Cc), blk>>>(Hs, 0, Dd,
                                        W1, (long)Dd * Dd, Dd,
                                        T, (long)Dd, Cc * Dd,
                                        Dd, nullptr, 0);

    // Phase B: out[z, j, c] = He_b[j,:] . T[z,c,:] + linear terms
    phaseB_k<<<dim3(2, 4, BL), blk>>>(He, T, Ls, Le, W2b, bs, out);
}

// round 4
// speedup vs baseline: 3.5089x; 3.5052x over previous
#include <cuda_runtime.h>
#include <cstdint>

#define Dd 768
#define Cc 256
#define BLn 1024

// Scratch (device globals: allocation-free rule)
__device__ float g_Htmp[BLn * Dd];
__device__ float g_Hs[BLn * Dd];
__device__ float g_He[BLn * Dd];
__device__ float g_Ls[BLn * Cc];
__device__ float g_Le[BLn * Cc];
__device__ float g_T[(size_t)BLn * Cc * Dd];     // T[bi][c][e]
__device__ float g_W1t[(size_t)Cc * Dd * Dd];    // W1t[c][e][d]
__device__ float g_Xr[BLn * Dd];
__device__ float g_w1r[Dd * Dd];
__device__ float g_w2r[Dd * Dd];
__device__ float g_w3r[Dd * Dd];
__device__ float g_w4r[Dd * Dd];
__device__ float g_W2r[Cc * 2 * Dd];

static __device__ __forceinline__ float rna(float x) {
    uint32_t u;
    asm("cvt.rna.tf32.f32 %0, %1;" : "=r"(u) : "f"(x));
    return __uint_as_float(u);
}
static __device__ __forceinline__ uint32_t smem_u32(const void* p) {
    uint32_t a;
    asm("{ .reg .u64 t; cvta.to.shared.u64 t, %1; cvt.u32.u64 %0, t; }" : "=r"(a) : "l"(p));
    return a;
}
static __device__ __forceinline__ void cp16(uint32_t dst, const float* src) {
    asm volatile("cp.async.cg.shared.global [%0], [%1], 16;" :: "r"(dst), "l"(src) : "memory");
}
static __device__ __forceinline__ void cp_commit() {
    asm volatile("cp.async.commit_group;" ::: "memory");
}
template <int N>
static __device__ __forceinline__ void cp_wait() {
    asm volatile("cp.async.wait_group %0;" :: "n"(N) : "memory");
}
static __device__ __forceinline__ void mma_tf32(float& c0, float& c1, float& c2, float& c3,
                                                uint32_t a0, uint32_t a1, uint32_t a2, uint32_t a3,
                                                uint32_t b0, uint32_t b1) {
    asm volatile(
        "mma.sync.aligned.m16n8k8.row.col.f32.tf32.tf32.f32 "
        "{%0,%1,%2,%3}, {%4,%5,%6,%7}, {%8,%9}, {%0,%1,%2,%3};"
        : "+f"(c0), "+f"(c1), "+f"(c2), "+f"(c3)
        : "r"(a0), "r"(a1), "r"(a2), "r"(a3), "r"(b0), "r"(b1));
}

// ---------------------------------------------------------------------------
// tf32 mma.sync GEMM: C[z][m,n] = sum_k A[z][m,k] * B[z][n,k], K=768.
// CTA tile 128x128, BK=32, 8 warps of 64x32, cp.async double buffer.
// modes: 0 plain | 1 rna(relu(+b1)) | 2 rna(+b1) | 3 rna | 4 biaffine epilogue
// ---------------------------------------------------------------------------
#define PADK 36
#define STG  (128 * PADK)          // floats per stage per operand
#define SMEM_BYTES (4 * STG * 4)   // 73728

__global__ void __launch_bounds__(256, 2)
gemm_tc(const float* A, long saz, int lda,
        const float* B, long sbz, int ldb,
        float* C, long scz, long ldc,
        int mode, const float* __restrict__ b1,
        const float* __restrict__ Lsg, const float* __restrict__ Leg,
        const float* __restrict__ W2bg, const float* __restrict__ biasg)
{
    extern __shared__ float smem[];
    float* As = smem;              // [2][128][36]
    float* Bs = smem + 2 * STG;    // [2][128][36]
    const uint32_t sbase = smem_u32(smem);
    const uint32_t bbase = sbase + 2 * STG * 4;

    const int tid = threadIdx.x;
    const int z = blockIdx.z;
    if (mode == 4) {
        A += (long)(z >> 9) * 512 * Dd;
        B += (long)z * Cc * Dd;
        C += (long)z * 512 * Cc;
    } else {
        A += z * saz; B += z * sbz; C += z * scz;
    }
    const int m0 = blockIdx.y * 128, n0 = blockIdx.x * 128;

    // producer mapping: 4 chunks of 16B per operand per thread
    const float* pa[4]; const float* pb[4];
    uint32_t qa[4], qb[4];
#pragma unroll
    for (int i = 0; i < 4; i++) {
        int cid = tid + i * 256, r = cid >> 3, cc = cid & 7;
        pa[i] = A + (long)(m0 + r) * lda + cc * 4;
        pb[i] = B + (long)(n0 + r) * ldb + cc * 4;
        uint32_t off = (uint32_t)(r * PADK + cc * 4) * 4;
        qa[i] = sbase + off;
        qb[i] = bbase + off;
    }

    float acc[4][4][4];
#pragma unroll
    for (int mi = 0; mi < 4; mi++)
#pragma unroll
        for (int ni = 0; ni < 4; ni++)
#pragma unroll
            for (int r = 0; r < 4; r++) acc[mi][ni][r] = 0.f;

    const int lane = tid & 31, w = tid >> 5;
    const int g = lane >> 2, tig = lane & 3;
    const int wm = w & 1, wn = w >> 1;           // warp tile: 64 (M) x 32 (N)

    // prologue: stage 0
#pragma unroll
    for (int i = 0; i < 4; i++) cp16(qa[i], pa[i]);
#pragma unroll
    for (int i = 0; i < 4; i++) cp16(qb[i], pb[i]);
    cp_commit();

    const uint32_t stgb = STG * 4;

    for (int k0 = 0; k0 < 24; k0++) {
        if (k0 < 23) {
            const uint32_t so = ((k0 + 1) & 1) * stgb;
            const long go = (long)(k0 + 1) * 32;
#pragma unroll
            for (int i = 0; i < 4; i++) cp16(qa[i] + so, pa[i] + go);
#pragma unroll
            for (int i = 0; i < 4; i++) cp16(qb[i] + so, pb[i] + go);
            cp_commit();
            cp_wait<1>();
        } else {
            cp_wait<0>();
        }
        __syncthreads();

        const float* a_s = As + (k0 & 1) * STG + (wm * 64 + tig) * 0; // base below
        const float* b_s = Bs + (k0 & 1) * STG;
        const float* aw = As + (k0 & 1) * STG + (wm * 64) * PADK;
        const float* bw = b_s + (wn * 32) * PADK;
        (void)a_s;

#pragma unroll
        for (int ks = 0; ks < 4; ks++) {
            const int kb = ks * 8 + tig;
            uint32_t af[4][4], bf[4][2];
#pragma unroll
            for (int mi = 0; mi < 4; mi++) {
                const float* p = aw + (mi * 16 + g) * PADK + kb;
                af[mi][0] = __float_as_uint(p[0]);
                af[mi][1] = __float_as_uint(p[8 * PADK]);
                af[mi][2] = __float_as_uint(p[4]);
                af[mi][3] = __float_as_uint(p[8 * PADK + 4]);
            }
#pragma unroll
            for (int ni = 0; ni < 4; ni++) {
                const float* p = bw + (ni * 8 + g) * PADK + kb;
                bf[ni][0] = __float_as_uint(p[0]);
                bf[ni][1] = __float_as_uint(p[4]);
            }
#pragma unroll
            for (int mi = 0; mi < 4; mi++)
#pragma unroll
                for (int ni = 0; ni < 4; ni++)
                    mma_tf32(acc[mi][ni][0], acc[mi][ni][1], acc[mi][ni][2], acc[mi][ni][3],
                             af[mi][0], af[mi][1], af[mi][2], af[mi][3],
                             bf[ni][0], bf[ni][1]);
        }
        __syncthreads();
    }

    // epilogue
    const float* lsr = nullptr; const float* leb = nullptr;
    if (mode == 4) {
        lsr = Lsg + (long)z * Cc;
        leb = Leg + (long)(z >> 9) * 512 * Cc;
    }
#pragma unroll
    for (int mi = 0; mi < 4; mi++) {
#pragma unroll
        for (int ni = 0; ni < 4; ni++) {
            const int col = n0 + wn * 32 + ni * 8 + tig * 2;
#pragma unroll
            for (int h = 0; h < 2; h++) {
                const int row = m0 + wm * 64 + mi * 16 + g + h * 8;
                float x0 = acc[mi][ni][h * 2];
                float x1 = acc[mi][ni][h * 2 + 1];
                if (mode == 1) {
                    x0 = rna(fmaxf(x0 + b1[col], 0.f));
                    x1 = rna(fmaxf(x1 + b1[col + 1], 0.f));
                } else if (mode == 2) {
                    x0 = rna(x0 + b1[col]);
                    x1 = rna(x1 + b1[col + 1]);
                } else if (mode == 3) {
                    x0 = rna(x0); x1 = rna(x1);
                } else if (mode == 4) {
                    const float* ler = leb + (long)row * Cc;
                    x0 += lsr[col] + ler[col] + W2bg[col] + biasg[col];
                    x1 += lsr[col + 1] + ler[col + 1] + W2bg[col + 1] + biasg[col + 1];
                }
                *(float2*)(C + (long)row * ldc + col) = make_float2(x0, x1);
            }
        }
    }
}

// W1t[c][e][d] = rna(W1[c][d][e])
__global__ void __launch_bounds__(256)
transpose_k(const float* __restrict__ W1, float* __restrict__ W1t)
{
    __shared__ float ts[32][33];
    const int c = blockIdx.z;
    const float* src = W1 + (size_t)c * Dd * Dd;
    float* dst = W1t + (size_t)c * Dd * Dd;
    const int d0 = blockIdx.y * 32, e0 = blockIdx.x * 32;
    const int x = threadIdx.x, y = threadIdx.y;
#pragma unroll
    for (int j = 0; j < 32; j += 8)
        ts[y + j][x] = src[(size_t)(d0 + y + j) * Dd + e0 + x];
    __syncthreads();
#pragma unroll
    for (int j = 0; j < 32; j += 8)
        dst[(size_t)(e0 + y + j) * Dd + d0 + x] = rna(ts[x][y + j]);
}

__global__ void round_k(const float* __restrict__ x, float* __restrict__ y, int n)
{
    for (int i = blockIdx.x * blockDim.x + threadIdx.x; i < n; i += gridDim.x * blockDim.x)
        y[i] = rna(x[i]);
}

extern "C" void kernel_launch(void* const* d_in, const int* in_sizes, int n_in,
                              void* d_out, int out_size)
{
    const float* hidden = (const float*)d_in[0];
    const float* sw1 = (const float*)d_in[1];
    const float* sb1 = (const float*)d_in[2];
    const float* sw2 = (const float*)d_in[3];
    const float* sb2 = (const float*)d_in[4];
    const float* ew1 = (const float*)d_in[5];
    const float* eb1 = (const float*)d_in[6];
    const float* ew2 = (const float*)d_in[7];
    const float* eb2 = (const float*)d_in[8];
    const float* W1  = (const float*)d_in[9];
    const float* W2w = (const float*)d_in[10];
    const float* W2b = (const float*)d_in[11];
    const float* bs  = (const float*)d_in[12];
    float* out = (float*)d_out;

    static int smem_set = 0;
    if (!smem_set) {
        cudaFuncSetAttribute(gemm_tc, cudaFuncAttributeMaxDynamicSharedMemorySize, SMEM_BYTES);
        smem_set = 1;
    }

    float *Htmp, *Hs, *He, *Ls, *Le, *T, *W1t, *Xr, *w1r, *w2r, *w3r, *w4r, *W2r;
    cudaGetSymbolAddress((void**)&Htmp, g_Htmp);
    cudaGetSymbolAddress((void**)&Hs, g_Hs);
    cudaGetSymbolAddress((void**)&He, g_He);
    cudaGetSymbolAddress((void**)&Ls, g_Ls);
    cudaGetSymbolAddress((void**)&Le, g_Le);
    cudaGetSymbolAddress((void**)&T, g_T);
    cudaGetSymbolAddress((void**)&W1t, g_W1t);
    cudaGetSymbolAddress((void**)&Xr, g_Xr);
    cudaGetSymbolAddress((void**)&w1r, g_w1r);
    cudaGetSymbolAddress((void**)&w2r, g_w2r);
    cudaGetSymbolAddress((void**)&w3r, g_w3r);
    cudaGetSymbolAddress((void**)&w4r, g_w4r);
    cudaGetSymbolAddress((void**)&W2r, g_W2r);

    // tf32-round inputs and weights
    round_k<<<192, 256>>>(hidden, Xr, BLn * Dd);
    round_k<<<192, 256>>>(sw1, w1r, Dd * Dd);
    round_k<<<192, 256>>>(sw2, w2r, Dd * Dd);
    round_k<<<192, 256>>>(ew1, w3r, Dd * Dd);
    round_k<<<192, 256>>>(ew2, w4r, Dd * Dd);
    round_k<<<192, 256>>>(W2w, W2r, Cc * 2 * Dd);
    transpose_k<<<dim3(24, 24, Cc), dim3(32, 8)>>>(W1, W1t);

    const dim3 blk(256);
    // MLPs (M=1024, N=768, K=768)
    gemm_tc<<<dim3(6, 8, 1), blk, SMEM_BYTES>>>(Xr, 0, Dd, w1r, 0, Dd, Htmp, 0, Dd,
                                                1, sb1, nullptr, nullptr, nullptr, nullptr);
    gemm_tc<<<dim3(6, 8, 1), blk, SMEM_BYTES>>>(Htmp, 0, Dd, w2r, 0, Dd, Hs, 0, Dd,
                                                2, sb2, nullptr, nullptr, nullptr, nullptr);
    gemm_tc<<<dim3(6, 8, 1), blk, SMEM_BYTES>>>(Xr, 0, Dd, w3r, 0, Dd, Htmp, 0, Dd,
                                                1, eb1, nullptr, nullptr, nullptr, nullptr);
    gemm_tc<<<dim3(6, 8, 1), blk, SMEM_BYTES>>>(Htmp, 0, Dd, w4r, 0, Dd, He, 0, Dd,
                                                2, eb2, nullptr, nullptr, nullptr, nullptr);
    // Ls / Le (M=1024, N=256, K=768); W2r row stride 1536
    gemm_tc<<<dim3(2, 8, 1), blk, SMEM_BYTES>>>(Hs, 0, Dd, W2r, 0, 2 * Dd, Ls, 0, Cc,
                                                0, nullptr, nullptr, nullptr, nullptr, nullptr);
    gemm_tc<<<dim3(2, 8, 1), blk, SMEM_BYTES>>>(He, 0, Dd, W2r + Dd, 0, 2 * Dd, Le, 0, Cc,
                                                0, nullptr, nullptr, nullptr, nullptr, nullptr);
    // Phase A: T[bi, c, e] = sum_d Hs[bi,d] * W1t[c,e,d]   (z = c)
    gemm_tc<<<dim3(6, 8, Cc), blk, SMEM_BYTES>>>(Hs, 0, Dd,
                                                 W1t, (long)Dd * Dd, Dd,
                                                 T, (long)Dd, (long)Cc * Dd,
                                                 3, nullptr, nullptr, nullptr, nullptr, nullptr);
    // Phase B: out[z, j, c] = sum_e He_b[j,e] * T[z,c,e] + linear   (z = bi)
    gemm_tc<<<dim3(2, 4, BLn), blk, SMEM_BYTES>>>(He, 0, Dd, T, 0, Dd, out, 0, Cc,
                                                  4, nullptr, Ls, Le, W2b, bs);
}